// round 1
// baseline (speedup 1.0000x reference)
#include <cuda_runtime.h>
#include <cuda_bf16.h>
#include <math.h>

#define NMOL 512
#define MA   64
#define FD   128
#define NF   16
#define DIN  (FD * (1 + NF))   // 2176
#define HID  512

// Scratch (allocation-free rule: __device__ globals)
__device__ float g_v[(size_t)NMOL * MA * DIN];   // 285 MB: v = [h, u]
__device__ float g_t[(size_t)NMOL * MA * HID];   // 67 MB: silu(v@W1+b1)

// ---------------------------------------------------------------------------
// Kernel A: per-molecule RBF message passing -> v = concat(h, u)
// grid = NMOL blocks, 256 threads. Dynamic smem = 64 KB.
// ---------------------------------------------------------------------------
__global__ __launch_bounds__(256) void build_v_kernel(
    const int* __restrict__ z, const float* __restrict__ r,
    const float* __restrict__ h, const float* __restrict__ distances,
    const float* __restrict__ widths)
{
    __shared__ float sr[MA][3];
    __shared__ float smk[MA];
    extern __shared__ float dyn[];
    float* sh = dyn;             // MA*FD  = 8192 floats
    float* sd = sh + MA * FD;    // MA*MA  = 4096 floats
    float* sw = sd + MA * MA;    // MA*MA  = 4096 floats

    const int n   = blockIdx.x;
    const int tid = threadIdx.x;

    if (tid < MA) {
        size_t base = ((size_t)n * MA + tid);
        sr[tid][0] = r[base * 3 + 0];
        sr[tid][1] = r[base * 3 + 1];
        sr[tid][2] = r[base * 3 + 2];
        smk[tid]   = (z[base] > -1) ? 1.0f : 0.0f;
    }

    const float* hb = h + (size_t)n * MA * FD;
    float*       vb = g_v + (size_t)n * MA * DIN;
    for (int i = tid; i < MA * FD; i += 256) {
        float val = hb[i];
        sh[i] = val;
        int a = i >> 7, c = i & 127;
        vb[(size_t)a * DIN + c] = val;   // v[:, 0:F] = h
    }
    __syncthreads();

    for (int i = tid; i < MA * MA; i += 256) {
        int a = i >> 6, b = i & 63;
        float dx = sr[a][0] - sr[b][0];
        float dy = sr[a][1] - sr[b][1];
        float dz = sr[a][2] - sr[b][2];
        sd[i] = sqrtf(fmaf(dx, dx, fmaf(dy, dy, fmaf(dz, dz, 1e-12f))));
    }
    __syncthreads();

    const int ty = tid >> 4;       // 0..15 -> 4 rows each
    const int tx = tid & 15;       // 0..15 -> 8 cols each
    const int a0 = ty * 4, c0 = tx * 8;

    for (int f = 0; f < NF; f++) {
        float mu      = distances[f];
        float inv_sig = 1.0f / widths[f];
        for (int i = tid; i < MA * MA; i += 256) {
            int a = i >> 6, b = i & 63;
            float dd = sd[i] - mu;
            sw[i] = smk[a] * smk[b] * 5.0f * __expf(-dd * dd * inv_sig);
        }
        __syncthreads();

        float acc[4][8];
        #pragma unroll
        for (int i = 0; i < 4; i++)
            #pragma unroll
            for (int j = 0; j < 8; j++) acc[i][j] = 0.0f;

        #pragma unroll 4
        for (int k = 0; k < MA; k++) {
            float wv[4], hv[8];
            #pragma unroll
            for (int i = 0; i < 4; i++) wv[i] = sw[(a0 + i) * MA + k];
            #pragma unroll
            for (int j = 0; j < 8; j++) hv[j] = sh[k * FD + c0 + j];
            #pragma unroll
            for (int i = 0; i < 4; i++)
                #pragma unroll
                for (int j = 0; j < 8; j++)
                    acc[i][j] = fmaf(wv[i], hv[j], acc[i][j]);
        }

        #pragma unroll
        for (int i = 0; i < 4; i++)
            #pragma unroll
            for (int j = 0; j < 8; j++)
                vb[(size_t)(a0 + i) * DIN + FD + f * FD + c0 + j] = acc[i][j];
        __syncthreads();
    }
}

// ---------------------------------------------------------------------------
// Kernel B: t = silu(v @ W1 + b1).  M=32768, N=512, K=2176.
// BM=BN=128, BK=8, TM=TN=8, 256 threads. grid = (4, 256).
// ---------------------------------------------------------------------------
__global__ __launch_bounds__(256) void gemm1_kernel(
    const float* __restrict__ W1, const float* __restrict__ b1)
{
    __shared__ float As[8][128];
    __shared__ float Bs[8][128];

    const int bx  = blockIdx.x;   // N tile: 0..3
    const int by  = blockIdx.y;   // M tile: 0..255
    const int tid = threadIdx.x;

    const float* A = g_v + (size_t)by * 128 * DIN;
    const float* B = W1 + bx * 128;
    float*       C = g_t + (size_t)by * 128 * HID + bx * 128;

    const int aRow = tid >> 1;            // 0..127
    const int aCol = (tid & 1) * 4;       // 0 or 4
    const int bRow = tid >> 5;            // 0..7
    const int bCol = (tid & 31) * 4;      // 0..124
    const int tRow = (tid >> 4) * 8;
    const int tCol = (tid & 15) * 8;

    float acc[8][8];
    #pragma unroll
    for (int i = 0; i < 8; i++)
        #pragma unroll
        for (int j = 0; j < 8; j++) acc[i][j] = 0.0f;

    for (int k0 = 0; k0 < DIN; k0 += 8) {
        float4 av = *(const float4*)(A + (size_t)aRow * DIN + k0 + aCol);
        As[aCol + 0][aRow] = av.x;
        As[aCol + 1][aRow] = av.y;
        As[aCol + 2][aRow] = av.z;
        As[aCol + 3][aRow] = av.w;
        *(float4*)&Bs[bRow][bCol] =
            *(const float4*)(B + (size_t)(k0 + bRow) * HID + bCol);
        __syncthreads();

        #pragma unroll
        for (int k = 0; k < 8; k++) {
            float regM[8], regN[8];
            *(float4*)&regM[0] = *(const float4*)&As[k][tRow];
            *(float4*)&regM[4] = *(const float4*)&As[k][tRow + 4];
            *(float4*)&regN[0] = *(const float4*)&Bs[k][tCol];
            *(float4*)&regN[4] = *(const float4*)&Bs[k][tCol + 4];
            #pragma unroll
            for (int i = 0; i < 8; i++)
                #pragma unroll
                for (int j = 0; j < 8; j++)
                    acc[i][j] = fmaf(regM[i], regN[j], acc[i][j]);
        }
        __syncthreads();
    }

    #pragma unroll
    for (int j = 0; j < 8; j++) {
        float bias = b1[bx * 128 + tCol + j];
        #pragma unroll
        for (int i = 0; i < 8; i++) {
            float x = acc[i][j] + bias;
            C[(size_t)(tRow + i) * HID + tCol + j] = x / (1.0f + __expf(-x));
        }
    }
}

// ---------------------------------------------------------------------------
// Kernel C: h_new = h + (t @ W2 + b2) * 0.1 * mask.  M=32768, N=128, K=512.
// grid = 256 blocks.
// ---------------------------------------------------------------------------
__global__ __launch_bounds__(256) void gemm2_kernel(
    const float* __restrict__ W2, const float* __restrict__ b2,
    const float* __restrict__ h, const int* __restrict__ z,
    float* __restrict__ out_h)
{
    __shared__ float As[8][128];
    __shared__ float Bs[8][128];

    const int by  = blockIdx.x;   // 0..255
    const int tid = threadIdx.x;

    const float* A = g_t + (size_t)by * 128 * HID;

    const int aRow = tid >> 1;
    const int aCol = (tid & 1) * 4;
    const int bRow = tid >> 5;
    const int bCol = (tid & 31) * 4;
    const int tRow = (tid >> 4) * 8;
    const int tCol = (tid & 15) * 8;

    float acc[8][8];
    #pragma unroll
    for (int i = 0; i < 8; i++)
        #pragma unroll
        for (int j = 0; j < 8; j++) acc[i][j] = 0.0f;

    for (int k0 = 0; k0 < HID; k0 += 8) {
        float4 av = *(const float4*)(A + (size_t)aRow * HID + k0 + aCol);
        As[aCol + 0][aRow] = av.x;
        As[aCol + 1][aRow] = av.y;
        As[aCol + 2][aRow] = av.z;
        As[aCol + 3][aRow] = av.w;
        *(float4*)&Bs[bRow][bCol] =
            *(const float4*)(W2 + (size_t)(k0 + bRow) * FD + bCol);
        __syncthreads();

        #pragma unroll
        for (int k = 0; k < 8; k++) {
            float regM[8], regN[8];
            *(float4*)&regM[0] = *(const float4*)&As[k][tRow];
            *(float4*)&regM[4] = *(const float4*)&As[k][tRow + 4];
            *(float4*)&regN[0] = *(const float4*)&Bs[k][tCol];
            *(float4*)&regN[4] = *(const float4*)&Bs[k][tCol + 4];
            #pragma unroll
            for (int i = 0; i < 8; i++)
                #pragma unroll
                for (int j = 0; j < 8; j++)
                    acc[i][j] = fmaf(regM[i], regN[j], acc[i][j]);
        }
        __syncthreads();
    }

    #pragma unroll
    for (int i = 0; i < 8; i++) {
        int row = by * 128 + tRow + i;            // global (n*MA + a)
        float msk = (z[row] > -1) ? 0.1f : 0.0f;  // UPDATE_RATIO*DECAY*mask
        #pragma unroll
        for (int j = 0; j < 8; j++) {
            int col = tCol + j;
            float v = acc[i][j] + b2[col];
            out_h[(size_t)row * FD + col] = h[(size_t)row * FD + col] + v * msk;
        }
    }
}

// ---------------------------------------------------------------------------
// Kernel D: pass-through outputs z (as float) and r, for tuple output layout.
// ---------------------------------------------------------------------------
__global__ void copy_zr_kernel(const int* __restrict__ z,
                               const float* __restrict__ r,
                               float* __restrict__ out)
{
    int i = blockIdx.x * 256 + threadIdx.x;
    const int nz = NMOL * MA;
    const int nr = NMOL * MA * 3;
    if (i < nz)            out[i] = (float)z[i];
    else if (i < nz + nr)  out[i] = r[i - nz];
}

extern "C" void kernel_launch(void* const* d_in, const int* in_sizes, int n_in,
                              void* d_out, int out_size)
{
    const int*   z         = (const int*)  d_in[0];
    const float* r         = (const float*)d_in[1];
    const float* h         = (const float*)d_in[2];
    const float* distances = (const float*)d_in[3];
    const float* widths    = (const float*)d_in[4];
    const float* W1        = (const float*)d_in[5];
    const float* b1        = (const float*)d_in[6];
    const float* W2        = (const float*)d_in[7];
    const float* b2        = (const float*)d_in[8];

    float* out   = (float*)d_out;
    float* out_h = out;
    const int nz = NMOL * MA;          // 32768
    const int nr = NMOL * MA * 3;      // 98304
    const int nh = NMOL * MA * FD;     // 4194304
    if (out_size >= nz + nr + nh) {
        // Output is concatenated (z, r, h_new)
        copy_zr_kernel<<<(nz + nr + 255) / 256, 256>>>(z, r, out);
        out_h = out + nz + nr;
    }

    cudaFuncSetAttribute(build_v_kernel,
                         cudaFuncAttributeMaxDynamicSharedMemorySize, 65536);

    build_v_kernel<<<NMOL, 256, 65536>>>(z, r, h, distances, widths);
    gemm1_kernel<<<dim3(4, 256), 256>>>(W1, b1);
    gemm2_kernel<<<256, 256>>>(W2, b2, h, z, out_h);
}

// round 2
// speedup vs baseline: 1.5702x; 1.5702x over previous
#include <cuda_runtime.h>
#include <cuda_bf16.h>
#include <math.h>
#include <stdint.h>

#define NMOL 512
#define MA   64
#define FD   128
#define NF   16
#define DIN  (FD * (1 + NF))   // 2176
#define HID  512

// Scratch (allocation-free rule: __device__ globals)
__device__ float g_v[(size_t)NMOL * MA * DIN];   // 285 MB: v = [h, u]
__device__ float g_t[(size_t)NMOL * MA * HID];   // 67 MB: silu(v@W1+b1)

__device__ __forceinline__ float to_tf32(float x) {
    float y;
    asm("cvt.rna.tf32.f32 %0, %1;" : "=f"(y) : "f"(x));
    return y;
}
__device__ __forceinline__ uint32_t f_as_u(float x) { return __float_as_uint(x); }

// ---------------------------------------------------------------------------
// Kernel A: per-molecule RBF message passing -> v = concat(h, u)
// ---------------------------------------------------------------------------
__global__ __launch_bounds__(256) void build_v_kernel(
    const int* __restrict__ z, const float* __restrict__ r,
    const float* __restrict__ h, const float* __restrict__ distances,
    const float* __restrict__ widths)
{
    __shared__ float sr[MA][3];
    __shared__ float smk[MA];
    extern __shared__ float dyn[];
    float* sh = dyn;             // MA*FD  = 8192 floats
    float* sd = sh + MA * FD;    // MA*MA
    float* sw = sd + MA * MA;    // MA*MA

    const int n   = blockIdx.x;
    const int tid = threadIdx.x;

    if (tid < MA) {
        size_t base = ((size_t)n * MA + tid);
        sr[tid][0] = r[base * 3 + 0];
        sr[tid][1] = r[base * 3 + 1];
        sr[tid][2] = r[base * 3 + 2];
        smk[tid]   = (z[base] > -1) ? 1.0f : 0.0f;
    }

    const float* hb = h + (size_t)n * MA * FD;
    float*       vb = g_v + (size_t)n * MA * DIN;
    for (int i = tid; i < MA * FD; i += 256) {
        float val = hb[i];
        sh[i] = val;
        int a = i >> 7, c = i & 127;
        vb[(size_t)a * DIN + c] = val;   // v[:, 0:F] = h
    }
    __syncthreads();

    for (int i = tid; i < MA * MA; i += 256) {
        int a = i >> 6, b = i & 63;
        float dx = sr[a][0] - sr[b][0];
        float dy = sr[a][1] - sr[b][1];
        float dz = sr[a][2] - sr[b][2];
        sd[i] = sqrtf(fmaf(dx, dx, fmaf(dy, dy, fmaf(dz, dz, 1e-12f))));
    }
    __syncthreads();

    const int ty = tid >> 4;
    const int tx = tid & 15;
    const int a0 = ty * 4, c0 = tx * 8;

    for (int f = 0; f < NF; f++) {
        float mu      = distances[f];
        float inv_sig = 1.0f / widths[f];
        for (int i = tid; i < MA * MA; i += 256) {
            int a = i >> 6, b = i & 63;
            float dd = sd[i] - mu;
            sw[i] = smk[a] * smk[b] * 5.0f * __expf(-dd * dd * inv_sig);
        }
        __syncthreads();

        float acc[4][8];
        #pragma unroll
        for (int i = 0; i < 4; i++)
            #pragma unroll
            for (int j = 0; j < 8; j++) acc[i][j] = 0.0f;

        #pragma unroll 4
        for (int k = 0; k < MA; k++) {
            float wv[4], hv[8];
            #pragma unroll
            for (int i = 0; i < 4; i++) wv[i] = sw[(a0 + i) * MA + k];
            #pragma unroll
            for (int j = 0; j < 8; j++) hv[j] = sh[k * FD + c0 + j];
            #pragma unroll
            for (int i = 0; i < 4; i++)
                #pragma unroll
                for (int j = 0; j < 8; j++)
                    acc[i][j] = fmaf(wv[i], hv[j], acc[i][j]);
        }

        #pragma unroll
        for (int i = 0; i < 4; i++)
            #pragma unroll
            for (int j = 0; j < 8; j++)
                vb[(size_t)(a0 + i) * DIN + FD + f * FD + c0 + j] = acc[i][j];
        __syncthreads();
    }
}

// ===========================================================================
// TF32 tensor-core GEMM skeleton.
// CTA: 128(M) x 128(N), BK=16. 8 warps: warp_m = wid&1 (64 rows),
// warp_n = wid>>1 (32 cols). Warp tile 64x32 = 4 m-atoms x 4 n-atoms of
// m16n8k8. SMEM XOR-swizzled (col ^= (k&3)<<3) -> conflict-free LDS.
// tf32 rounding applied once at global->smem store.
// ===========================================================================

struct FragState {
    uint32_t lane, g, q, warp_m, warp_n;
    int m_ld, c0, krow, n4;   // loader indices
};

__device__ __forceinline__ FragState frag_init(int tid) {
    FragState s;
    s.lane   = tid & 31;
    s.g      = s.lane >> 2;
    s.q      = s.lane & 3;
    int wid  = tid >> 5;
    s.warp_m = (wid & 1) * 64;
    s.warp_n = (wid >> 1) * 32;
    s.m_ld   = tid & 127;
    s.c0     = (tid >> 7) * 4;       // 0 or 4 (second load at +8)
    s.krow   = tid >> 5;             // 0..7 (second at +8)
    s.n4     = (s.lane) * 4;         // 0..124
    return s;
}

#define STS_A(Asb, s, av, kofs)                                              \
    {                                                                        \
        _Pragma("unroll")                                                    \
        for (int i = 0; i < 4; i++) {                                        \
            float v = ((const float*)&(av))[i];                              \
            (Asb)[((s).c0 + (kofs) + i) * 128 + ((s).m_ld ^ (i << 3))] =     \
                to_tf32(v);                                                  \
        }                                                                    \
    }

#define STS_B(Bsb, s, bv, kofs)                                              \
    {                                                                        \
        float4 t;                                                            \
        t.x = to_tf32((bv).x); t.y = to_tf32((bv).y);                        \
        t.z = to_tf32((bv).z); t.w = to_tf32((bv).w);                        \
        int kk = (s).krow + (kofs);                                          \
        *(float4*)&(Bsb)[kk * 128 + ((s).n4 ^ ((kk & 3) << 3))] = t;         \
    }

__device__ __forceinline__ void mma_compute(
    const float* __restrict__ Asb, const float* __restrict__ Bsb,
    const FragState& s, float d[4][4][4])
{
    #pragma unroll
    for (int kk = 0; kk < 16; kk += 8) {
        uint32_t a[4][4];
        #pragma unroll
        for (int am = 0; am < 4; am++) {
            int m0 = s.warp_m + am * 16 + s.g;
            int cswz = s.q << 3;
            const float* r0 = &Asb[(kk + s.q) * 128];
            const float* r4 = &Asb[(kk + s.q + 4) * 128];
            a[am][0] = f_as_u(r0[m0 ^ cswz]);
            a[am][1] = f_as_u(r0[(m0 + 8) ^ cswz]);
            a[am][2] = f_as_u(r4[m0 ^ cswz]);
            a[am][3] = f_as_u(r4[(m0 + 8) ^ cswz]);
        }
        uint32_t b[4][2];
        #pragma unroll
        for (int an = 0; an < 4; an++) {
            int nn = s.warp_n + an * 8 + s.g;
            int col = nn ^ (s.q << 3);
            b[an][0] = f_as_u(Bsb[(kk + s.q) * 128 + col]);
            b[an][1] = f_as_u(Bsb[(kk + s.q + 4) * 128 + col]);
        }
        #pragma unroll
        for (int am = 0; am < 4; am++)
            #pragma unroll
            for (int an = 0; an < 4; an++)
                asm volatile(
                    "mma.sync.aligned.m16n8k8.row.col.f32.tf32.tf32.f32 "
                    "{%0,%1,%2,%3}, {%4,%5,%6,%7}, {%8,%9}, {%0,%1,%2,%3};\n"
                    : "+f"(d[am][an][0]), "+f"(d[am][an][1]),
                      "+f"(d[am][an][2]), "+f"(d[am][an][3])
                    : "r"(a[am][0]), "r"(a[am][1]),
                      "r"(a[am][2]), "r"(a[am][3]),
                      "r"(b[an][0]), "r"(b[an][1]));
    }
}

// ---------------------------------------------------------------------------
// Kernel B: t = silu(v @ W1 + b1).  M=32768, N=512, K=2176. grid(4, 256).
// ---------------------------------------------------------------------------
__global__ __launch_bounds__(256) void gemm1_tc_kernel(
    const float* __restrict__ W1, const float* __restrict__ b1)
{
    __shared__ float As[2][16 * 128];
    __shared__ float Bs[2][16 * 128];

    const int bx  = blockIdx.x;
    const int by  = blockIdx.y;
    const int tid = threadIdx.x;
    FragState s = frag_init(tid);

    const float* A = g_v + (size_t)by * 128 * DIN;   // lda = DIN
    const float* B = W1 + bx * 128;                  // ldb = HID

    float d[4][4][4];
    #pragma unroll
    for (int am = 0; am < 4; am++)
        #pragma unroll
        for (int an = 0; an < 4; an++)
            #pragma unroll
            for (int i = 0; i < 4; i++) d[am][an][i] = 0.0f;

    const float* aRowPtr = A + (size_t)s.m_ld * DIN;
    float4 a0s, a1s, b0s, b1s;

    a0s = *(const float4*)(aRowPtr + s.c0);
    a1s = *(const float4*)(aRowPtr + s.c0 + 8);
    b0s = *(const float4*)(B + (size_t)s.krow * HID + s.n4);
    b1s = *(const float4*)(B + (size_t)(s.krow + 8) * HID + s.n4);

    int buf = 0;
    STS_A(As[buf], s, a0s, 0); STS_A(As[buf], s, a1s, 8);
    STS_B(Bs[buf], s, b0s, 0); STS_B(Bs[buf], s, b1s, 8);
    __syncthreads();

    for (int k0 = 16;; k0 += 16) {
        bool has_next = (k0 < DIN);
        if (has_next) {
            a0s = *(const float4*)(aRowPtr + k0 + s.c0);
            a1s = *(const float4*)(aRowPtr + k0 + s.c0 + 8);
            b0s = *(const float4*)(B + (size_t)(k0 + s.krow) * HID + s.n4);
            b1s = *(const float4*)(B + (size_t)(k0 + s.krow + 8) * HID + s.n4);
        }
        mma_compute(As[buf], Bs[buf], s, d);
        if (!has_next) break;
        buf ^= 1;
        STS_A(As[buf], s, a0s, 0); STS_A(As[buf], s, a1s, 8);
        STS_B(Bs[buf], s, b0s, 0); STS_B(Bs[buf], s, b1s, 8);
        __syncthreads();
    }

    // Epilogue: bias + SiLU -> g_t
    float* C = g_t + (size_t)by * 128 * HID + bx * 128;
    #pragma unroll
    for (int am = 0; am < 4; am++) {
        int r0 = s.warp_m + am * 16 + s.g;
        #pragma unroll
        for (int an = 0; an < 4; an++) {
            int cn = s.warp_n + an * 8 + s.q * 2;
            float bb0 = b1[bx * 128 + cn];
            float bb1 = b1[bx * 128 + cn + 1];
            float x0 = d[am][an][0] + bb0;
            float x1 = d[am][an][1] + bb1;
            float x2 = d[am][an][2] + bb0;
            float x3 = d[am][an][3] + bb1;
            float2 lo = make_float2(x0 / (1.0f + __expf(-x0)),
                                    x1 / (1.0f + __expf(-x1)));
            float2 hi = make_float2(x2 / (1.0f + __expf(-x2)),
                                    x3 / (1.0f + __expf(-x3)));
            *(float2*)&C[(size_t)r0 * HID + cn]       = lo;
            *(float2*)&C[(size_t)(r0 + 8) * HID + cn] = hi;
        }
    }
}

// ---------------------------------------------------------------------------
// Kernel C: h_new = h + (t @ W2 + b2)*0.1*mask.  M=32768, N=128, K=512.
// ---------------------------------------------------------------------------
__global__ __launch_bounds__(256) void gemm2_tc_kernel(
    const float* __restrict__ W2, const float* __restrict__ b2,
    const float* __restrict__ h, const int* __restrict__ z,
    float* __restrict__ out_h)
{
    __shared__ float As[2][16 * 128];
    __shared__ float Bs[2][16 * 128];

    const int by  = blockIdx.x;
    const int tid = threadIdx.x;
    FragState s = frag_init(tid);

    const float* A = g_t + (size_t)by * 128 * HID;   // lda = HID
    const float* B = W2;                             // ldb = FD

    float d[4][4][4];
    #pragma unroll
    for (int am = 0; am < 4; am++)
        #pragma unroll
        for (int an = 0; an < 4; an++)
            #pragma unroll
            for (int i = 0; i < 4; i++) d[am][an][i] = 0.0f;

    const float* aRowPtr = A + (size_t)s.m_ld * HID;
    float4 a0s, a1s, b0s, b1s;

    a0s = *(const float4*)(aRowPtr + s.c0);
    a1s = *(const float4*)(aRowPtr + s.c0 + 8);
    b0s = *(const float4*)(B + (size_t)s.krow * FD + s.n4);
    b1s = *(const float4*)(B + (size_t)(s.krow + 8) * FD + s.n4);

    int buf = 0;
    STS_A(As[buf], s, a0s, 0); STS_A(As[buf], s, a1s, 8);
    STS_B(Bs[buf], s, b0s, 0); STS_B(Bs[buf], s, b1s, 8);
    __syncthreads();

    for (int k0 = 16;; k0 += 16) {
        bool has_next = (k0 < HID);
        if (has_next) {
            a0s = *(const float4*)(aRowPtr + k0 + s.c0);
            a1s = *(const float4*)(aRowPtr + k0 + s.c0 + 8);
            b0s = *(const float4*)(B + (size_t)(k0 + s.krow) * FD + s.n4);
            b1s = *(const float4*)(B + (size_t)(k0 + s.krow + 8) * FD + s.n4);
        }
        mma_compute(As[buf], Bs[buf], s, d);
        if (!has_next) break;
        buf ^= 1;
        STS_A(As[buf], s, a0s, 0); STS_A(As[buf], s, a1s, 8);
        STS_B(Bs[buf], s, b0s, 0); STS_B(Bs[buf], s, b1s, 8);
        __syncthreads();
    }

    // Epilogue: bias, *0.1*mask, residual add
    #pragma unroll
    for (int am = 0; am < 4; am++) {
        int r0 = by * 128 + s.warp_m + am * 16 + s.g;
        int r8 = r0 + 8;
        float m0 = (z[r0] > -1) ? 0.1f : 0.0f;
        float m8 = (z[r8] > -1) ? 0.1f : 0.0f;
        #pragma unroll
        for (int an = 0; an < 4; an++) {
            int cn = s.warp_n + an * 8 + s.q * 2;
            float bb0 = b2[cn], bb1 = b2[cn + 1];
            float2 h0 = *(const float2*)&h[(size_t)r0 * FD + cn];
            float2 h8 = *(const float2*)&h[(size_t)r8 * FD + cn];
            float2 o0, o8;
            o0.x = h0.x + (d[am][an][0] + bb0) * m0;
            o0.y = h0.y + (d[am][an][1] + bb1) * m0;
            o8.x = h8.x + (d[am][an][2] + bb0) * m8;
            o8.y = h8.y + (d[am][an][3] + bb1) * m8;
            *(float2*)&out_h[(size_t)r0 * FD + cn] = o0;
            *(float2*)&out_h[(size_t)r8 * FD + cn] = o8;
        }
    }
}

// ---------------------------------------------------------------------------
// Kernel D: pass-through z (as float) and r for the tuple output layout.
// ---------------------------------------------------------------------------
__global__ void copy_zr_kernel(const int* __restrict__ z,
                               const float* __restrict__ r,
                               float* __restrict__ out)
{
    int i = blockIdx.x * 256 + threadIdx.x;
    const int nz = NMOL * MA;
    const int nr = NMOL * MA * 3;
    if (i < nz)            out[i] = (float)z[i];
    else if (i < nz + nr)  out[i] = r[i - nz];
}

extern "C" void kernel_launch(void* const* d_in, const int* in_sizes, int n_in,
                              void* d_out, int out_size)
{
    const int*   z         = (const int*)  d_in[0];
    const float* r         = (const float*)d_in[1];
    const float* h         = (const float*)d_in[2];
    const float* distances = (const float*)d_in[3];
    const float* widths    = (const float*)d_in[4];
    const float* W1        = (const float*)d_in[5];
    const float* b1        = (const float*)d_in[6];
    const float* W2        = (const float*)d_in[7];
    const float* b2        = (const float*)d_in[8];

    float* out   = (float*)d_out;
    float* out_h = out;
    const int nz = NMOL * MA;
    const int nr = NMOL * MA * 3;
    const int nh = NMOL * MA * FD;
    if (out_size >= nz + nr + nh) {
        copy_zr_kernel<<<(nz + nr + 255) / 256, 256>>>(z, r, out);
        out_h = out + nz + nr;
    }

    cudaFuncSetAttribute(build_v_kernel,
                         cudaFuncAttributeMaxDynamicSharedMemorySize, 65536);

    build_v_kernel<<<NMOL, 256, 65536>>>(z, r, h, distances, widths);
    gemm1_tc_kernel<<<dim3(4, 256), 256>>>(W1, b1);
    gemm2_tc_kernel<<<256, 256>>>(W2, b2, h, z, out_h);
}

// round 5
// speedup vs baseline: 6.7383x; 4.2915x over previous
#include <cuda_runtime.h>
#include <cuda_fp16.h>
#include <math.h>
#include <stdint.h>

#define NMOL 512
#define MA   64
#define FD   128
#define NF   16
#define DIN  (FD * (1 + NF))   // 2176
#define HID  512
#define MTOT (NMOL * MA)       // 32768

// Scratch (allocation-free rule: __device__ globals)
__device__ __align__(256) __half g_v[(size_t)MTOT * DIN];    // 142 MB
__device__ __align__(256) __half g_w1t[(size_t)HID * DIN];   // [N][K]
__device__ __align__(256) __half g_w2t[(size_t)FD * HID];    // [N][K]
__device__ __align__(256) __half g_t[(size_t)MTOT * HID];    // 33 MB

// ===================== low-level helpers ===================================
__device__ __forceinline__ uint32_t smem_u32(const void* p) {
    uint32_t a;
    asm("{ .reg .u64 t; cvta.to.shared.u64 t, %1; cvt.u32.u64 %0, t; }"
        : "=r"(a) : "l"(p));
    return a;
}
#define CP_ASYNC16(s, g) \
    asm volatile("cp.async.cg.shared.global [%0], [%1], 16;" :: "r"(s), "l"(g))
#define CP_COMMIT() asm volatile("cp.async.commit_group;")
#define CP_WAIT1()  asm volatile("cp.async.wait_group 1;" ::: "memory")

__device__ __forceinline__ void ldsm_x4(uint32_t& r0, uint32_t& r1,
                                        uint32_t& r2, uint32_t& r3, uint32_t a) {
    asm volatile("ldmatrix.sync.aligned.m8n8.x4.shared.b16 {%0,%1,%2,%3}, [%4];"
                 : "=r"(r0), "=r"(r1), "=r"(r2), "=r"(r3) : "r"(a));
}
__device__ __forceinline__ void ldsm_x4_t(uint32_t& r0, uint32_t& r1,
                                          uint32_t& r2, uint32_t& r3, uint32_t a) {
    asm volatile("ldmatrix.sync.aligned.m8n8.x4.trans.shared.b16 {%0,%1,%2,%3}, [%4];"
                 : "=r"(r0), "=r"(r1), "=r"(r2), "=r"(r3) : "r"(a));
}
__device__ __forceinline__ void mma16816(float d[4],
    uint32_t a0, uint32_t a1, uint32_t a2, uint32_t a3, uint32_t b0, uint32_t b1) {
    asm volatile(
        "mma.sync.aligned.m16n8k16.row.col.f32.f16.f16.f32 "
        "{%0,%1,%2,%3}, {%4,%5,%6,%7}, {%8,%9}, {%0,%1,%2,%3};"
        : "+f"(d[0]), "+f"(d[1]), "+f"(d[2]), "+f"(d[3])
        : "r"(a0), "r"(a1), "r"(a2), "r"(a3), "r"(b0), "r"(b1));
}
// 64B-row tile swizzle: 4x 16B chunks per row, phys chunk = c ^ ((row>>1)&3)
__device__ __forceinline__ uint32_t swz64(uint32_t base, int row, int chunk) {
    return base + row * 64 + (((chunk ^ (row >> 1)) & 3) << 4);
}

// ===================== weight prep (f32 -> transposed fp16) ================
__global__ void prep_w1_kernel(const float* __restrict__ W1) {
    __shared__ float tile[32][33];
    int n0 = blockIdx.x * 32, k0 = blockIdx.y * 32;
    int tx = threadIdx.x, ty = threadIdx.y;
    for (int rr = ty; rr < 32; rr += 8)
        tile[rr][tx] = W1[(size_t)(k0 + rr) * HID + n0 + tx];
    __syncthreads();
    for (int rr = ty; rr < 32; rr += 8)
        g_w1t[(size_t)(n0 + rr) * DIN + k0 + tx] = __float2half(tile[tx][rr]);
}
__global__ void prep_w2_kernel(const float* __restrict__ W2) {
    __shared__ float tile[32][33];
    int n0 = blockIdx.x * 32, k0 = blockIdx.y * 32;
    int tx = threadIdx.x, ty = threadIdx.y;
    for (int rr = ty; rr < 32; rr += 8)
        tile[rr][tx] = W2[(size_t)(k0 + rr) * FD + n0 + tx];
    __syncthreads();
    for (int rr = ty; rr < 32; rr += 8)
        g_w2t[(size_t)(n0 + rr) * HID + k0 + tx] = __float2half(tile[tx][rr]);
}

// ===========================================================================
// Kernel A: per-molecule RBF message passing -> v (fp16) = concat(h, u)
// RBF weights computed fp32 (exp), aggregation on tensor cores (fp16 mma).
// dyn smem: shh 16KB (h fp16, swizzled) + swh 8KB (w fp16, swizzled) + sd 16KB
// ===========================================================================
__global__ __launch_bounds__(256) void build_v_kernel(
    const int* __restrict__ z, const float* __restrict__ r,
    const float* __restrict__ h, const float* __restrict__ distances,
    const float* __restrict__ widths)
{
    __shared__ float sr[MA][3];
    __shared__ float smk[MA];
    __shared__ float s_mu[NF], s_isig[NF];
    extern __shared__ char dynv[];
    char*  shh_c = dynv;                       // 64 x 128 half, 256B rows
    char*  swh_c = dynv + 16384;               // 64 x 64 half, 128B rows
    float* sd    = (float*)(dynv + 16384 + 8192);
    const uint32_t shh_b = smem_u32(shh_c);
    const uint32_t swh_b = smem_u32(swh_c);

    const int n   = blockIdx.x;
    const int tid = threadIdx.x;

    if (tid < MA) {
        size_t base = ((size_t)n * MA + tid);
        sr[tid][0] = r[base * 3 + 0];
        sr[tid][1] = r[base * 3 + 1];
        sr[tid][2] = r[base * 3 + 2];
        smk[tid]   = (z[base] > -1) ? 1.0f : 0.0f;
    }
    if (tid < NF) {
        s_mu[tid]   = distances[tid];
        s_isig[tid] = 1.0f / widths[tid];
    }

    // h -> shh (fp16, swizzled) and v[:, 0:FD] (fp16)
    const float* hb = h + (size_t)n * MA * FD;
    const size_t vrow = (size_t)n * MA;
    for (int V = tid; V < 1024; V += 256) {
        int b = V >> 4, ch = V & 15;
        const float* src = hb + b * FD + ch * 8;
        __half hh[8];
        #pragma unroll
        for (int i = 0; i < 8; i++) hh[i] = __float2half(src[i]);
        *(uint4*)(shh_c + b * 256 + ((ch ^ (b & 7)) << 4)) = *(uint4*)hh;
        *(uint4*)&g_v[(vrow + b) * DIN + ch * 8] = *(uint4*)hh;
    }
    __syncthreads();

    // pairwise distances (fp32)
    for (int i = tid; i < MA * MA; i += 256) {
        int a = i >> 6, b = i & 63;
        float dx = sr[a][0] - sr[b][0];
        float dy = sr[a][1] - sr[b][1];
        float dz = sr[a][2] - sr[b][2];
        sd[i] = sqrtf(fmaf(dx, dx, fmaf(dy, dy, fmaf(dz, dz, 1e-12f))));
    }
    __syncthreads();

    const int lane = tid & 31, w = tid >> 5;
    const int g = lane >> 2, q = lane & 3;
    const int t = lane >> 3, rin = lane & 7;
    const int wa = (w & 3) * 16;        // m-atom row base (0,16,32,48)
    const int nh = (w >> 2) * 64;       // n half (0 or 64)

    for (int f = 0; f < NF; f++) {
        const float mu = s_mu[f], inv_sig = s_isig[f];
        // w (fp32 exp) -> swh fp16, swizzled: addr = a*128 + ((c^(a&7))<<4) + (b&7)*2
        for (int i = tid; i < MA * MA; i += 256) {
            int a = i >> 6, b = i & 63;
            float dd = sd[i] - mu;
            float wv = smk[a] * smk[b] * 5.0f * __expf(-dd * dd * inv_sig);
            *(__half*)(swh_c + a * 128 + (((b >> 3) ^ (a & 7)) << 4) + (b & 7) * 2)
                = __float2half(wv);
        }
        __syncthreads();

        // u-tile: per warp one m16 x 64(n) x 64(k) mma block
        float dacc[8][4];
        #pragma unroll
        for (int na = 0; na < 8; na++)
            #pragma unroll
            for (int i = 0; i < 4; i++) dacc[na][i] = 0.0f;

        #pragma unroll
        for (int ks = 0; ks < 4; ks++) {
            uint32_t a0, a1, a2, a3;
            {
                int arow = wa + (t & 1) * 8 + rin;
                int ach  = ks * 2 + (t >> 1);
                ldsm_x4(a0, a1, a2, a3,
                        swh_b + arow * 128 + (((ach ^ (arow & 7)) & 7) << 4));
            }
            #pragma unroll
            for (int np = 0; np < 4; np++) {
                uint32_t r0, r1, r2, r3;
                int brow = ks * 16 + (t & 1) * 8 + rin;
                int bch  = (nh >> 3) + np * 2 + (t >> 1);
                ldsm_x4_t(r0, r1, r2, r3,
                          shh_b + brow * 256 + (((bch ^ (brow & 7)) & 15) << 4));
                mma16816(dacc[np * 2],     a0, a1, a2, a3, r0, r1);
                mma16816(dacc[np * 2 + 1], a0, a1, a2, a3, r2, r3);
            }
        }

        // store u -> v[:, FD + f*128 ...] fp16
        #pragma unroll
        for (int na = 0; na < 8; na++) {
            int ar  = wa + g;
            int col = FD + f * FD + nh + na * 8 + q * 2;
            __half2 lo = __floats2half2_rn(dacc[na][0], dacc[na][1]);
            __half2 hi = __floats2half2_rn(dacc[na][2], dacc[na][3]);
            *(__half2*)&g_v[(vrow + ar) * DIN + col]     = lo;
            *(__half2*)&g_v[(vrow + ar + 8) * DIN + col] = hi;
        }
        __syncthreads();
    }
}

// ===========================================================================
// fp16 GEMM core: CTA 128x128, BK=32, 3-stage cp.async, 8 warps (2m x 4n),
// warp tile 64x32, ldmatrix fragments, m16n8k16 f32-accum.
// smem: 3 x (8KB A + 8KB B) = 48KB. A,B tiles both [128 rows][32 k] fp16.
// ===========================================================================
__device__ __forceinline__ void g_load_stage(uint32_t sA, uint32_t sB,
    const __half* __restrict__ A, int lda, const __half* __restrict__ B, int ldb,
    int kc, int tid)
{
    #pragma unroll
    for (int i = 0; i < 2; i++) {
        int V = tid + i * 256;
        int m = V >> 2, c = V & 3;
        CP_ASYNC16(swz64(sA, m, c), A + (size_t)m * lda + kc + c * 8);
        CP_ASYNC16(swz64(sB, m, c), B + (size_t)m * ldb + kc + c * 8);
    }
}

__device__ __forceinline__ void g_compute(uint32_t sA, uint32_t sB, int tid,
                                          float d[4][4][4])
{
    const int lane = tid & 31, w = tid >> 5;
    const int wm = (w & 1) * 64, wn = (w >> 1) * 32;
    const int t = lane >> 3, rin = lane & 7;

    uint32_t bf[4][4];
    {
        int brow = wn + (lane & 7);
        int bch  = lane >> 3;
        #pragma unroll
        for (int na = 0; na < 4; na++)
            ldsm_x4(bf[na][0], bf[na][1], bf[na][2], bf[na][3],
                    swz64(sB, brow + na * 8, bch));
    }
    #pragma unroll
    for (int ks = 0; ks < 2; ks++) {
        uint32_t af[4][4];
        int arow = wm + (t & 1) * 8 + rin;
        int ach  = ks * 2 + (t >> 1);
        #pragma unroll
        for (int ma = 0; ma < 4; ma++)
            ldsm_x4(af[ma][0], af[ma][1], af[ma][2], af[ma][3],
                    swz64(sA, arow + ma * 16, ach));
        #pragma unroll
        for (int ma = 0; ma < 4; ma++)
            #pragma unroll
            for (int na = 0; na < 4; na++)
                mma16816(d[ma][na], af[ma][0], af[ma][1], af[ma][2], af[ma][3],
                         bf[na][ks * 2], bf[na][ks * 2 + 1]);
    }
}

__device__ __forceinline__ void gemm_main(
    const __half* __restrict__ A, int lda, const __half* __restrict__ B, int ldb,
    int nchunks, uint32_t sA0, uint32_t sB0, int tid, float d[4][4][4])
{
    g_load_stage(sA0,        sB0,        A, lda, B, ldb, 0,  tid); CP_COMMIT();
    g_load_stage(sA0 + 8192, sB0 + 8192, A, lda, B, ldb, 32, tid); CP_COMMIT();
    for (int c = 0; c < nchunks; c++) {
        CP_WAIT1();
        __syncthreads();
        int nc = c + 2;
        if (nc < nchunks) {
            int slot = nc - (nc / 3) * 3;
            g_load_stage(sA0 + slot * 8192, sB0 + slot * 8192,
                         A, lda, B, ldb, nc * 32, tid);
        }
        CP_COMMIT();
        int cs = c - (c / 3) * 3;
        g_compute(sA0 + cs * 8192, sB0 + cs * 8192, tid, d);
    }
}

// ---------------------------------------------------------------------------
// Kernel B: t = silu(v @ W1 + b1) -> g_t fp16. M=32768, N=512, K=2176.
// ---------------------------------------------------------------------------
__global__ __launch_bounds__(256) void gemm1_kernel(const float* __restrict__ b1)
{
    extern __shared__ __align__(128) char smem[];
    uint32_t sA0 = smem_u32(smem), sB0 = sA0 + 3 * 8192;
    const int tid = threadIdx.x;
    const int bx = blockIdx.x, by = blockIdx.y;

    const __half* A = g_v  + (size_t)by * 128 * DIN;
    const __half* B = g_w1t + (size_t)bx * 128 * DIN;

    float d[4][4][4];
    #pragma unroll
    for (int ma = 0; ma < 4; ma++)
        #pragma unroll
        for (int na = 0; na < 4; na++)
            #pragma unroll
            for (int i = 0; i < 4; i++) d[ma][na][i] = 0.0f;

    gemm_main(A, DIN, B, DIN, DIN / 32, sA0, sB0, tid, d);

    const int lane = tid & 31, w = tid >> 5;
    const int g2 = lane >> 2, q = lane & 3;
    const int wm = (w & 1) * 64, wn = (w >> 1) * 32;
    #pragma unroll
    for (int ma = 0; ma < 4; ma++) {
        int r0 = by * 128 + wm + ma * 16 + g2;
        #pragma unroll
        for (int na = 0; na < 4; na++) {
            int cn = bx * 128 + wn + na * 8 + q * 2;
            float bb0 = b1[cn], bb1 = b1[cn + 1];
            float x0 = d[ma][na][0] + bb0;
            float x1 = d[ma][na][1] + bb1;
            float x2 = d[ma][na][2] + bb0;
            float x3 = d[ma][na][3] + bb1;
            x0 = x0 / (1.0f + __expf(-x0));
            x1 = x1 / (1.0f + __expf(-x1));
            x2 = x2 / (1.0f + __expf(-x2));
            x3 = x3 / (1.0f + __expf(-x3));
            *(__half2*)&g_t[(size_t)r0 * HID + cn]       = __floats2half2_rn(x0, x1);
            *(__half2*)&g_t[(size_t)(r0 + 8) * HID + cn] = __floats2half2_rn(x2, x3);
        }
    }
}

// ---------------------------------------------------------------------------
// Kernel C: h_new = h + (t @ W2 + b2)*0.1*mask. M=32768, N=128, K=512.
// ---------------------------------------------------------------------------
__global__ __launch_bounds__(256) void gemm2_kernel(
    const float* __restrict__ b2, const float* __restrict__ h,
    const int* __restrict__ z, float* __restrict__ out_h)
{
    extern __shared__ __align__(128) char smem[];
    uint32_t sA0 = smem_u32(smem), sB0 = sA0 + 3 * 8192;
    const int tid = threadIdx.x;
    const int by = blockIdx.x;

    const __half* A = g_t + (size_t)by * 128 * HID;
    const __half* B = g_w2t;

    float d[4][4][4];
    #pragma unroll
    for (int ma = 0; ma < 4; ma++)
        #pragma unroll
        for (int na = 0; na < 4; na++)
            #pragma unroll
            for (int i = 0; i < 4; i++) d[ma][na][i] = 0.0f;

    gemm_main(A, HID, B, HID, HID / 32, sA0, sB0, tid, d);

    const int lane = tid & 31, w = tid >> 5;
    const int g2 = lane >> 2, q = lane & 3;
    const int wm = (w & 1) * 64, wn = (w >> 1) * 32;
    #pragma unroll
    for (int ma = 0; ma < 4; ma++) {
        int r0 = by * 128 + wm + ma * 16 + g2;
        int r8 = r0 + 8;
        float m0 = (z[r0] > -1) ? 0.1f : 0.0f;
        float m8 = (z[r8] > -1) ? 0.1f : 0.0f;
        #pragma unroll
        for (int na = 0; na < 4; na++) {
            int cn = wn + na * 8 + q * 2;
            float bb0 = b2[cn], bb1 = b2[cn + 1];
            float2 h0 = *(const float2*)&h[(size_t)r0 * FD + cn];
            float2 h8 = *(const float2*)&h[(size_t)r8 * FD + cn];
            float2 o0, o8;
            o0.x = h0.x + (d[ma][na][0] + bb0) * m0;
            o0.y = h0.y + (d[ma][na][1] + bb1) * m0;
            o8.x = h8.x + (d[ma][na][2] + bb0) * m8;
            o8.y = h8.y + (d[ma][na][3] + bb1) * m8;
            *(float2*)&out_h[(size_t)r0 * FD + cn] = o0;
            *(float2*)&out_h[(size_t)r8 * FD + cn] = o8;
        }
    }
}

// ---------------------------------------------------------------------------
// Kernel D: pass-through z (as float) and r for the tuple output layout.
// ---------------------------------------------------------------------------
__global__ void copy_zr_kernel(const int* __restrict__ z,
                               const float* __restrict__ r,
                               float* __restrict__ out)
{
    int i = blockIdx.x * 256 + threadIdx.x;
    const int nz = NMOL * MA;
    const int nr = NMOL * MA * 3;
    if (i < nz)            out[i] = (float)z[i];
    else if (i < nz + nr)  out[i] = r[i - nz];
}

extern "C" void kernel_launch(void* const* d_in, const int* in_sizes, int n_in,
                              void* d_out, int out_size)
{
    const int*   z         = (const int*)  d_in[0];
    const float* r         = (const float*)d_in[1];
    const float* h         = (const float*)d_in[2];
    const float* distances = (const float*)d_in[3];
    const float* widths    = (const float*)d_in[4];
    const float* W1        = (const float*)d_in[5];
    const float* b1        = (const float*)d_in[6];
    const float* W2        = (const float*)d_in[7];
    const float* b2        = (const float*)d_in[8];

    float* out   = (float*)d_out;
    float* out_h = out;
    const int nz = NMOL * MA;
    const int nr = NMOL * MA * 3;
    const int nh = NMOL * MA * FD;
    if (out_size >= nz + nr + nh) {
        copy_zr_kernel<<<(nz + nr + 255) / 256, 256>>>(z, r, out);
        out_h = out + nz + nr;
    }

    cudaFuncSetAttribute(build_v_kernel,
                         cudaFuncAttributeMaxDynamicSharedMemorySize, 40960);
    cudaFuncSetAttribute(gemm1_kernel,
                         cudaFuncAttributeMaxDynamicSharedMemorySize, 49152);
    cudaFuncSetAttribute(gemm2_kernel,
                         cudaFuncAttributeMaxDynamicSharedMemorySize, 49152);

    prep_w1_kernel<<<dim3(HID / 32, DIN / 32), dim3(32, 8)>>>(W1);
    prep_w2_kernel<<<dim3(FD / 32, HID / 32), dim3(32, 8)>>>(W2);
    build_v_kernel<<<NMOL, 256, 40960>>>(z, r, h, distances, widths);
    gemm1_kernel<<<dim3(HID / 128, MTOT / 128), 256, 49152>>>(b1);
    gemm2_kernel<<<MTOT / 128, 256, 49152>>>(b2, h, z, out_h);
}